// round 1
// baseline (speedup 1.0000x reference)
#include <cuda_runtime.h>

#define NN 50000
#define NE 200000
#define DD 128
#define RR 4
#define HH 64
#define TE 32
#define NTHREADS 256
#define NSM 152

// Scratch (static device memory — no runtime allocation)
__device__ float g_acc[NN * HH];        // per-node hidden-space accumulator (12.8 MB)
__device__ int   g_bucket[RR * NE];     // edge ids compacted by relation (3.2 MB)
__device__ int   g_cnt[RR];

__global__ void zero_kernel() {
    int i = blockIdx.x * blockDim.x + threadIdx.x;
    if (i < NN * HH / 4) {
        ((float4*)g_acc)[i] = make_float4(0.f, 0.f, 0.f, 0.f);
    }
    if (i < RR) g_cnt[i] = 0;
}

__global__ void bin_kernel(const int* __restrict__ etype) {
    __shared__ int s_cnt[RR];
    __shared__ int s_base[RR];
    int t = threadIdx.x;
    if (t < RR) s_cnt[t] = 0;
    __syncthreads();
    int e = blockIdx.x * blockDim.x + t;
    int r = -1, pos = 0;
    if (e < NE) { r = etype[e]; pos = atomicAdd(&s_cnt[r], 1); }
    __syncthreads();
    if (t < RR) s_base[t] = atomicAdd(&g_cnt[t], s_cnt[t]);
    __syncthreads();
    if (r >= 0) g_bucket[r * NE + s_base[r] + pos] = e;
}

// ---------------------------------------------------------------------------
// Edge kernel: for each edge e of relation r:
//   h1 = relu(x_src @ Wr1[r] + br1[r])        128 -> 64
//   h2 = relu(h1 @ Wr2[r] + br2[r])            64 -> 64
//   msg = relu(h2 @ Wr3[r] + br3[r])           64 -> 128
//   p   = msg @ Wn1[(1+r)*D : (2+r)*D]        128 -> 64   (linear fusion)
//   atomicAdd(g_acc[dst], p)
// One block per (relation, slot). All weights for the relation in SMEM.
// ---------------------------------------------------------------------------
__global__ __launch_bounds__(NTHREADS, 1)
void edge_kernel(const float* __restrict__ nf,
                 const int* __restrict__ esrc, const int* __restrict__ edst,
                 const float* __restrict__ Wr1, const float* __restrict__ br1,
                 const float* __restrict__ Wr2, const float* __restrict__ br2,
                 const float* __restrict__ Wr3, const float* __restrict__ br3,
                 const float* __restrict__ Wn1) {
    extern __shared__ float sm[];
    float* sW1 = sm;                      // [128][64]
    float* sW2 = sW1 + DD * HH;           // [64][64]
    float* sW3 = sW2 + HH * HH;           // [64][128]
    float* sWn = sW3 + HH * DD;           // [128][64]
    float* sb1 = sWn + DD * HH;           // 64
    float* sb2 = sb1 + HH;                // 64
    float* sb3 = sb2 + HH;                // 128
    float* sXM = sb3 + DD;                // [32][132]  x tile, later reused for msg
    float* sH1 = sXM + TE * 132;          // [32][68]
    float* sH2 = sH1 + TE * 68;           // [32][68]
    int*   sSrc = (int*)(sH2 + TE * 68);  // 32
    int*   sDst = sSrc + TE;              // 32

    const int t     = threadIdx.x;
    const int rel   = blockIdx.x & (RR - 1);
    const int bslot = blockIdx.x / RR;
    const int nb    = gridDim.x / RR;

    // Load this relation's weights into SMEM (contiguous slices)
    const float* gW1 = Wr1 + rel * DD * HH;
    const float* gW2 = Wr2 + rel * HH * HH;
    const float* gW3 = Wr3 + rel * HH * DD;
    const float* gWn = Wn1 + (1 + rel) * DD * HH;   // rows (1+rel)*D .. of Wn1
    for (int i = t; i < DD * HH / 4; i += NTHREADS) ((float4*)sW1)[i] = ((const float4*)gW1)[i];
    for (int i = t; i < HH * HH / 4; i += NTHREADS) ((float4*)sW2)[i] = ((const float4*)gW2)[i];
    for (int i = t; i < HH * DD / 4; i += NTHREADS) ((float4*)sW3)[i] = ((const float4*)gW3)[i];
    for (int i = t; i < DD * HH / 4; i += NTHREADS) ((float4*)sWn)[i] = ((const float4*)gWn)[i];
    if (t < HH) { sb1[t] = br1[rel * HH + t]; sb2[t] = br2[rel * HH + t]; }
    if (t < DD) { sb3[t] = br3[rel * DD + t]; }

    const int cnt    = g_cnt[rel];
    const int ntiles = (cnt + TE - 1) / TE;
    const int row = t >> 3;     // 0..31 : edge within tile
    const int sj  = t & 7;      // 0..7  : column-group

    for (int tile = bslot; tile < ntiles; tile += nb) {
        __syncthreads();   // protect sXM/sSrc reuse (also orders weight loads on iter 0)
        if (t < TE) {
            int idx = tile * TE + t;
            if (idx < cnt) {
                int e = g_bucket[rel * NE + idx];
                sSrc[t] = esrc[e];
                sDst[t] = edst[e];
            } else { sSrc[t] = 0; sDst[t] = -1; }
        }
        __syncthreads();

        // Gather x_src tile: 8 threads per row, 4 float4 each (coalesced per row)
        {
            const float* xr = nf + sSrc[row] * DD;
            #pragma unroll
            for (int i = 0; i < 4; i++) {
                int d0 = sj * 4 + i * 32;
                *(float4*)(sXM + row * 132 + d0) = *(const float4*)(xr + d0);
            }
        }
        __syncthreads();

        // ---- Layer 1: [32,128] @ [128,64] -> sH1, relu ----
        {
            const int c0 = sj * 8;
            float4 a0 = make_float4(0.f,0.f,0.f,0.f), a1 = a0;
            const float* xrow = sXM + row * 132;
            #pragma unroll 4
            for (int k = 0; k < DD; k++) {
                float a = xrow[k];
                float4 b0 = *(const float4*)(sW1 + k * HH + c0);
                float4 b1 = *(const float4*)(sW1 + k * HH + c0 + 4);
                a0.x = fmaf(a, b0.x, a0.x); a0.y = fmaf(a, b0.y, a0.y);
                a0.z = fmaf(a, b0.z, a0.z); a0.w = fmaf(a, b0.w, a0.w);
                a1.x = fmaf(a, b1.x, a1.x); a1.y = fmaf(a, b1.y, a1.y);
                a1.z = fmaf(a, b1.z, a1.z); a1.w = fmaf(a, b1.w, a1.w);
            }
            float* hrow = sH1 + row * 68 + c0;
            const float* bb = sb1 + c0;
            hrow[0] = fmaxf(a0.x + bb[0], 0.f); hrow[1] = fmaxf(a0.y + bb[1], 0.f);
            hrow[2] = fmaxf(a0.z + bb[2], 0.f); hrow[3] = fmaxf(a0.w + bb[3], 0.f);
            hrow[4] = fmaxf(a1.x + bb[4], 0.f); hrow[5] = fmaxf(a1.y + bb[5], 0.f);
            hrow[6] = fmaxf(a1.z + bb[6], 0.f); hrow[7] = fmaxf(a1.w + bb[7], 0.f);
        }
        __syncthreads();

        // ---- Layer 2: [32,64] @ [64,64] -> sH2, relu ----
        {
            const int c0 = sj * 8;
            float4 a0 = make_float4(0.f,0.f,0.f,0.f), a1 = a0;
            const float* hrow = sH1 + row * 68;
            #pragma unroll 4
            for (int k = 0; k < HH; k++) {
                float a = hrow[k];
                float4 b0 = *(const float4*)(sW2 + k * HH + c0);
                float4 b1 = *(const float4*)(sW2 + k * HH + c0 + 4);
                a0.x = fmaf(a, b0.x, a0.x); a0.y = fmaf(a, b0.y, a0.y);
                a0.z = fmaf(a, b0.z, a0.z); a0.w = fmaf(a, b0.w, a0.w);
                a1.x = fmaf(a, b1.x, a1.x); a1.y = fmaf(a, b1.y, a1.y);
                a1.z = fmaf(a, b1.z, a1.z); a1.w = fmaf(a, b1.w, a1.w);
            }
            float* orow = sH2 + row * 68 + c0;
            const float* bb = sb2 + c0;
            orow[0] = fmaxf(a0.x + bb[0], 0.f); orow[1] = fmaxf(a0.y + bb[1], 0.f);
            orow[2] = fmaxf(a0.z + bb[2], 0.f); orow[3] = fmaxf(a0.w + bb[3], 0.f);
            orow[4] = fmaxf(a1.x + bb[4], 0.f); orow[5] = fmaxf(a1.y + bb[5], 0.f);
            orow[6] = fmaxf(a1.z + bb[6], 0.f); orow[7] = fmaxf(a1.w + bb[7], 0.f);
        }
        __syncthreads();

        // ---- Layer 3: [32,64] @ [64,128] -> msg in sXM (reuse), relu ----
        {
            const int c0 = sj * 16;
            float4 acc[4];
            #pragma unroll
            for (int q = 0; q < 4; q++) acc[q] = make_float4(0.f,0.f,0.f,0.f);
            const float* hrow = sH2 + row * 68;
            #pragma unroll 4
            for (int k = 0; k < HH; k++) {
                float a = hrow[k];
                #pragma unroll
                for (int q = 0; q < 4; q++) {
                    float4 b = *(const float4*)(sW3 + k * DD + c0 + q * 4);
                    acc[q].x = fmaf(a, b.x, acc[q].x); acc[q].y = fmaf(a, b.y, acc[q].y);
                    acc[q].z = fmaf(a, b.z, acc[q].z); acc[q].w = fmaf(a, b.w, acc[q].w);
                }
            }
            float* mrow = sXM + row * 132 + c0;
            #pragma unroll
            for (int q = 0; q < 4; q++) {
                const float* bb = sb3 + c0 + q * 4;
                mrow[q*4+0] = fmaxf(acc[q].x + bb[0], 0.f);
                mrow[q*4+1] = fmaxf(acc[q].y + bb[1], 0.f);
                mrow[q*4+2] = fmaxf(acc[q].z + bb[2], 0.f);
                mrow[q*4+3] = fmaxf(acc[q].w + bb[3], 0.f);
            }
        }
        __syncthreads();

        // ---- Layer 4 (fused projection): [32,128] @ [128,64] -> atomic into g_acc ----
        {
            const int c0 = sj * 8;
            float4 a0 = make_float4(0.f,0.f,0.f,0.f), a1 = a0;
            const float* mrow = sXM + row * 132;
            #pragma unroll 4
            for (int k = 0; k < DD; k++) {
                float a = mrow[k];
                float4 b0 = *(const float4*)(sWn + k * HH + c0);
                float4 b1 = *(const float4*)(sWn + k * HH + c0 + 4);
                a0.x = fmaf(a, b0.x, a0.x); a0.y = fmaf(a, b0.y, a0.y);
                a0.z = fmaf(a, b0.z, a0.z); a0.w = fmaf(a, b0.w, a0.w);
                a1.x = fmaf(a, b1.x, a1.x); a1.y = fmaf(a, b1.y, a1.y);
                a1.z = fmaf(a, b1.z, a1.z); a1.w = fmaf(a, b1.w, a1.w);
            }
            int dst = sDst[row];
            if (dst >= 0) {
                float* p = g_acc + dst * HH + c0;
                atomicAdd(p + 0, a0.x); atomicAdd(p + 1, a0.y);
                atomicAdd(p + 2, a0.z); atomicAdd(p + 3, a0.w);
                atomicAdd(p + 4, a1.x); atomicAdd(p + 5, a1.y);
                atomicAdd(p + 6, a1.z); atomicAdd(p + 7, a1.w);
            }
        }
    }
}

// ---------------------------------------------------------------------------
// Node kernel:
//   pre = relu(nf) @ Wn1[0:D] + g_acc + bn1 ; h = relu(pre)
//   h   = relu(h @ Wn2 + bn2)
//   out = h @ Wn3 + bn3
// ---------------------------------------------------------------------------
__global__ __launch_bounds__(NTHREADS, 1)
void node_kernel(const float* __restrict__ nf,
                 const float* __restrict__ Wn1, const float* __restrict__ bn1,
                 const float* __restrict__ Wn2, const float* __restrict__ bn2,
                 const float* __restrict__ Wn3, const float* __restrict__ bn3,
                 float* __restrict__ out) {
    extern __shared__ float sm[];
    float* sW1 = sm;                     // [128][64] (first D rows of Wn1)
    float* sW2 = sW1 + DD * HH;          // [64][64]
    float* sW3 = sW2 + HH * HH;          // [64][128]
    float* sb1 = sW3 + HH * DD;
    float* sb2 = sb1 + HH;
    float* sb3 = sb2 + HH;
    float* sX  = sb3 + DD;               // [32][132]
    float* sH1 = sX + TE * 132;          // [32][68]
    float* sH2 = sH1 + TE * 68;

    const int t = threadIdx.x;
    for (int i = t; i < DD * HH / 4; i += NTHREADS) ((float4*)sW1)[i] = ((const float4*)Wn1)[i];
    for (int i = t; i < HH * HH / 4; i += NTHREADS) ((float4*)sW2)[i] = ((const float4*)Wn2)[i];
    for (int i = t; i < HH * DD / 4; i += NTHREADS) ((float4*)sW3)[i] = ((const float4*)Wn3)[i];
    if (t < HH) { sb1[t] = bn1[t]; sb2[t] = bn2[t]; }
    if (t < DD) sb3[t] = bn3[t];

    const int ntiles = (NN + TE - 1) / TE;
    const int row = t >> 3;
    const int sj  = t & 7;

    for (int tile = blockIdx.x; tile < ntiles; tile += gridDim.x) {
        __syncthreads();
        const int n = tile * TE + row;
        if (n < NN) {
            const float* xr = nf + n * DD;
            #pragma unroll
            for (int i = 0; i < 4; i++) {
                int d0 = sj * 4 + i * 32;
                float4 v = *(const float4*)(xr + d0);
                v.x = fmaxf(v.x, 0.f); v.y = fmaxf(v.y, 0.f);
                v.z = fmaxf(v.z, 0.f); v.w = fmaxf(v.w, 0.f);
                *(float4*)(sX + row * 132 + d0) = v;
            }
        }
        __syncthreads();

        // ---- Layer 1 (+ edge aggregate + bias, relu) ----
        {
            const int c0 = sj * 8;
            float4 a0 = make_float4(0.f,0.f,0.f,0.f), a1 = a0;
            const float* xrow = sX + row * 132;
            #pragma unroll 4
            for (int k = 0; k < DD; k++) {
                float a = xrow[k];
                float4 b0 = *(const float4*)(sW1 + k * HH + c0);
                float4 b1 = *(const float4*)(sW1 + k * HH + c0 + 4);
                a0.x = fmaf(a, b0.x, a0.x); a0.y = fmaf(a, b0.y, a0.y);
                a0.z = fmaf(a, b0.z, a0.z); a0.w = fmaf(a, b0.w, a0.w);
                a1.x = fmaf(a, b1.x, a1.x); a1.y = fmaf(a, b1.y, a1.y);
                a1.z = fmaf(a, b1.z, a1.z); a1.w = fmaf(a, b1.w, a1.w);
            }
            float* hrow = sH1 + row * 68 + c0;
            if (n < NN) {
                const float* ga = g_acc + n * HH + c0;
                const float* bb = sb1 + c0;
                hrow[0] = fmaxf(a0.x + ga[0] + bb[0], 0.f);
                hrow[1] = fmaxf(a0.y + ga[1] + bb[1], 0.f);
                hrow[2] = fmaxf(a0.z + ga[2] + bb[2], 0.f);
                hrow[3] = fmaxf(a0.w + ga[3] + bb[3], 0.f);
                hrow[4] = fmaxf(a1.x + ga[4] + bb[4], 0.f);
                hrow[5] = fmaxf(a1.y + ga[5] + bb[5], 0.f);
                hrow[6] = fmaxf(a1.z + ga[6] + bb[6], 0.f);
                hrow[7] = fmaxf(a1.w + ga[7] + bb[7], 0.f);
            } else {
                #pragma unroll
                for (int j = 0; j < 8; j++) hrow[j] = 0.f;
            }
        }
        __syncthreads();

        // ---- Layer 2 ----
        {
            const int c0 = sj * 8;
            float4 a0 = make_float4(0.f,0.f,0.f,0.f), a1 = a0;
            const float* hrow = sH1 + row * 68;
            #pragma unroll 4
            for (int k = 0; k < HH; k++) {
                float a = hrow[k];
                float4 b0 = *(const float4*)(sW2 + k * HH + c0);
                float4 b1 = *(const float4*)(sW2 + k * HH + c0 + 4);
                a0.x = fmaf(a, b0.x, a0.x); a0.y = fmaf(a, b0.y, a0.y);
                a0.z = fmaf(a, b0.z, a0.z); a0.w = fmaf(a, b0.w, a0.w);
                a1.x = fmaf(a, b1.x, a1.x); a1.y = fmaf(a, b1.y, a1.y);
                a1.z = fmaf(a, b1.z, a1.z); a1.w = fmaf(a, b1.w, a1.w);
            }
            float* orow = sH2 + row * 68 + c0;
            const float* bb = sb2 + c0;
            orow[0] = fmaxf(a0.x + bb[0], 0.f); orow[1] = fmaxf(a0.y + bb[1], 0.f);
            orow[2] = fmaxf(a0.z + bb[2], 0.f); orow[3] = fmaxf(a0.w + bb[3], 0.f);
            orow[4] = fmaxf(a1.x + bb[4], 0.f); orow[5] = fmaxf(a1.y + bb[5], 0.f);
            orow[6] = fmaxf(a1.z + bb[6], 0.f); orow[7] = fmaxf(a1.w + bb[7], 0.f);
        }
        __syncthreads();

        // ---- Layer 3 -> out ----
        {
            const int c0 = sj * 16;
            float4 acc[4];
            #pragma unroll
            for (int q = 0; q < 4; q++) acc[q] = make_float4(0.f,0.f,0.f,0.f);
            const float* hrow = sH2 + row * 68;
            #pragma unroll 4
            for (int k = 0; k < HH; k++) {
                float a = hrow[k];
                #pragma unroll
                for (int q = 0; q < 4; q++) {
                    float4 b = *(const float4*)(sW3 + k * DD + c0 + q * 4);
                    acc[q].x = fmaf(a, b.x, acc[q].x); acc[q].y = fmaf(a, b.y, acc[q].y);
                    acc[q].z = fmaf(a, b.z, acc[q].z); acc[q].w = fmaf(a, b.w, acc[q].w);
                }
            }
            if (n < NN) {
                float* orow = out + n * DD + c0;
                #pragma unroll
                for (int q = 0; q < 4; q++) {
                    const float* bb = sb3 + c0 + q * 4;
                    float4 v;
                    v.x = acc[q].x + bb[0]; v.y = acc[q].y + bb[1];
                    v.z = acc[q].z + bb[2]; v.w = acc[q].w + bb[3];
                    *(float4*)(orow + q * 4) = v;
                }
            }
        }
    }
}

extern "C" void kernel_launch(void* const* d_in, const int* in_sizes, int n_in,
                              void* d_out, int out_size) {
    const float* nf   = (const float*)d_in[0];
    const int*   esrc = (const int*)d_in[1];
    const int*   edst = (const int*)d_in[2];
    const int*   etyp = (const int*)d_in[3];
    const float* Wr1  = (const float*)d_in[4];
    const float* br1  = (const float*)d_in[5];
    const float* Wr2  = (const float*)d_in[6];
    const float* br2  = (const float*)d_in[7];
    const float* Wr3  = (const float*)d_in[8];
    const float* br3  = (const float*)d_in[9];
    const float* Wn1  = (const float*)d_in[10];
    const float* bn1  = (const float*)d_in[11];
    const float* Wn2  = (const float*)d_in[12];
    const float* bn2  = (const float*)d_in[13];
    const float* Wn3  = (const float*)d_in[14];
    const float* bn3  = (const float*)d_in[15];
    float* out = (float*)d_out;

    const int EDGE_SMEM = (DD*HH + HH*HH + HH*DD + DD*HH + HH + HH + DD
                           + TE*132 + 2*TE*68) * 4 + 2 * TE * 4;   // ~150 KB
    const int NODE_SMEM = (DD*HH + HH*HH + HH*DD + HH + HH + DD
                           + TE*132 + 2*TE*68) * 4;                 // ~117 KB

    cudaFuncSetAttribute(edge_kernel, cudaFuncAttributeMaxDynamicSharedMemorySize, EDGE_SMEM);
    cudaFuncSetAttribute(node_kernel, cudaFuncAttributeMaxDynamicSharedMemorySize, NODE_SMEM);

    zero_kernel<<<(NN * HH / 4 + NTHREADS - 1) / NTHREADS, NTHREADS>>>();
    bin_kernel<<<(NE + NTHREADS - 1) / NTHREADS, NTHREADS>>>(etyp);
    edge_kernel<<<NSM, NTHREADS, EDGE_SMEM>>>(nf, esrc, edst,
                                              Wr1, br1, Wr2, br2, Wr3, br3, Wn1);
    node_kernel<<<NSM, NTHREADS, NODE_SMEM>>>(nf, Wn1, bn1, Wn2, bn2, Wn3, bn3, out);
}

// round 3
// speedup vs baseline: 5.1189x; 5.1189x over previous
#include <cuda_runtime.h>

#define NN 50000
#define NE 200000
#define DD 128
#define RR 4
#define HH 64
#define TE 64            // rows (edges/nodes) per tile
#define XS (DD + 4)      // x/msg tile stride (132: mult of 4, /4 odd)
#define HS (HH + 4)      // hidden tile stride (68: mult of 4, /4 odd)
#define NTHREADS 256
#define NSM 152

// Scratch (static device memory — no runtime allocation)
__device__ float g_acc[NN * HH];
__device__ int   g_bucket[RR * NE];
__device__ int   g_cnt[RR];

__global__ void zero_kernel() {
    int i = blockIdx.x * blockDim.x + threadIdx.x;
    if (i < NN * HH / 4) ((float4*)g_acc)[i] = make_float4(0.f, 0.f, 0.f, 0.f);
    if (i < RR) g_cnt[i] = 0;
}

__global__ void bin_kernel(const int* __restrict__ etype) {
    __shared__ int s_cnt[RR];
    __shared__ int s_base[RR];
    int t = threadIdx.x;
    if (t < RR) s_cnt[t] = 0;
    __syncthreads();
    int e = blockIdx.x * blockDim.x + t;
    int r = -1, pos = 0;
    if (e < NE) { r = etype[e]; pos = atomicAdd(&s_cnt[r], 1); }
    __syncthreads();
    if (t < RR) s_base[t] = atomicAdd(&g_cnt[t], s_cnt[t]);
    __syncthreads();
    if (r >= 0) g_bucket[r * NE + s_base[r] + pos] = e;
}

// 4x4 register-tile GEMM, row-major activations [rows][AST], weights [K][WS].
// All float4 accesses 16B-aligned (AST, WS, k0, r0, c0 all mult of 4).
template<int K, int WS, int AST>
__device__ __forceinline__ void gemm44(const float* __restrict__ act,
                                       const float* __restrict__ W,
                                       int r0, int c0, float acc[4][4]) {
    #pragma unroll 2
    for (int k0 = 0; k0 < K; k0 += 4) {
        float4 a0 = *(const float4*)(act + (r0 + 0) * AST + k0);
        float4 a1 = *(const float4*)(act + (r0 + 1) * AST + k0);
        float4 a2 = *(const float4*)(act + (r0 + 2) * AST + k0);
        float4 a3 = *(const float4*)(act + (r0 + 3) * AST + k0);
        float ar[4][4] = {{a0.x,a0.y,a0.z,a0.w},{a1.x,a1.y,a1.z,a1.w},
                          {a2.x,a2.y,a2.z,a2.w},{a3.x,a3.y,a3.z,a3.w}};
        #pragma unroll
        for (int kk = 0; kk < 4; kk++) {
            float4 w = *(const float4*)(W + (k0 + kk) * WS + c0);
            #pragma unroll
            for (int i = 0; i < 4; i++) {
                acc[i][0] = fmaf(ar[i][kk], w.x, acc[i][0]);
                acc[i][1] = fmaf(ar[i][kk], w.y, acc[i][1]);
                acc[i][2] = fmaf(ar[i][kk], w.z, acc[i][2]);
                acc[i][3] = fmaf(ar[i][kk], w.w, acc[i][3]);
            }
        }
    }
}

// 8x4 register-tile GEMM for the 128-col layer (W stride DD).
template<int K, int AST>
__device__ __forceinline__ void gemm84(const float* __restrict__ act,
                                       const float* __restrict__ W,
                                       int r0, int c0, float acc[8][4]) {
    #pragma unroll 2
    for (int k0 = 0; k0 < K; k0 += 4) {
        float ar[8][4];
        #pragma unroll
        for (int i = 0; i < 8; i++) {
            float4 a = *(const float4*)(act + (r0 + i) * AST + k0);
            ar[i][0] = a.x; ar[i][1] = a.y; ar[i][2] = a.z; ar[i][3] = a.w;
        }
        #pragma unroll
        for (int kk = 0; kk < 4; kk++) {
            float4 w = *(const float4*)(W + (k0 + kk) * DD + c0);
            #pragma unroll
            for (int i = 0; i < 8; i++) {
                acc[i][0] = fmaf(ar[i][kk], w.x, acc[i][0]);
                acc[i][1] = fmaf(ar[i][kk], w.y, acc[i][1]);
                acc[i][2] = fmaf(ar[i][kk], w.z, acc[i][2]);
                acc[i][3] = fmaf(ar[i][kk], w.w, acc[i][3]);
            }
        }
    }
}

// ---------------------------------------------------------------------------
// Edge kernel. Per edge of relation r:
//   h1 = relu(x_src@Wr1[r]+br1); h2 = relu(h1@Wr2[r]+br2)
//   msg = relu(h2@Wr3[r]+br3);  p = msg@Wn1[(1+r)D:(2+r)D];  g_acc[dst] += p
// ---------------------------------------------------------------------------
__global__ __launch_bounds__(NTHREADS, 1)
void edge_kernel(const float* __restrict__ nf,
                 const int* __restrict__ esrc, const int* __restrict__ edst,
                 const float* __restrict__ Wr1, const float* __restrict__ br1,
                 const float* __restrict__ Wr2, const float* __restrict__ br2,
                 const float* __restrict__ Wr3, const float* __restrict__ br3,
                 const float* __restrict__ Wn1) {
    extern __shared__ float sm[];
    float* sW1 = sm;                      // [128][64]
    float* sW2 = sW1 + DD * HH;           // [64][64]
    float* sW3 = sW2 + HH * HH;           // [64][128]
    float* sWn = sW3 + HH * DD;           // [128][64]
    float* sb1 = sWn + DD * HH;
    float* sb2 = sb1 + HH;
    float* sb3 = sb2 + HH;                // 128
    float* sX  = sb3 + DD;                // [64][XS]  x tile, reused for msg
    float* sH1 = sX + TE * XS;            // [64][HS]
    float* sH2 = sH1 + TE * HS;           // [64][HS]
    int* sSrc = (int*)(sH2 + TE * HS);    // 64
    int* sDst = sSrc + TE;                // 64

    const int t     = threadIdx.x;
    const int rel   = blockIdx.x & (RR - 1);
    const int bslot = blockIdx.x / RR;
    const int nb    = gridDim.x / RR;

    const float* gW1 = Wr1 + rel * DD * HH;
    const float* gW2 = Wr2 + rel * HH * HH;
    const float* gW3 = Wr3 + rel * HH * DD;
    const float* gWn = Wn1 + (1 + rel) * DD * HH;
    for (int i = t; i < DD * HH / 4; i += NTHREADS) ((float4*)sW1)[i] = ((const float4*)gW1)[i];
    for (int i = t; i < HH * HH / 4; i += NTHREADS) ((float4*)sW2)[i] = ((const float4*)gW2)[i];
    for (int i = t; i < HH * DD / 4; i += NTHREADS) ((float4*)sW3)[i] = ((const float4*)gW3)[i];
    for (int i = t; i < DD * HH / 4; i += NTHREADS) ((float4*)sWn)[i] = ((const float4*)gWn)[i];
    if (t < HH) { sb1[t] = br1[rel * HH + t]; sb2[t] = br2[rel * HH + t]; }
    if (t < DD) { sb3[t] = br3[rel * DD + t]; }

    const int cnt    = g_cnt[rel];
    const int ntiles = (cnt + TE - 1) / TE;

    const int c4 = (t & 15) * 4, r4 = (t >> 4) * 4;   // 4x4 map (64-col layers)
    const int c8 = (t & 31) * 4, r8 = (t >> 5) * 8;   // 8x4 map (128-col layer)
    const int grow = t >> 2, gj = t & 3;              // gather map

    for (int tile = bslot; tile < ntiles; tile += nb) {
        __syncthreads();                  // protect sX/sSrc reuse
        if (t < TE) {
            int idx = tile * TE + t;
            if (idx < cnt) {
                int e = g_bucket[rel * NE + idx];
                sSrc[t] = esrc[e];
                sDst[t] = edst[e];
            } else { sSrc[t] = 0; sDst[t] = -1; }
        }
        __syncthreads();

        // Gather x_src tile (row-major)
        {
            const float* xr = nf + (long)sSrc[grow] * DD;
            float* dr = sX + grow * XS;
            #pragma unroll
            for (int i = 0; i < 8; i++) {
                int d0 = gj * 4 + i * 16;
                *(float4*)(dr + d0) = *(const float4*)(xr + d0);
            }
        }
        __syncthreads();

        // L1: [64,128]@[128,64] -> sH1
        {
            float acc[4][4] = {};
            gemm44<DD, HH, XS>(sX, sW1, r4, c4, acc);
            #pragma unroll
            for (int i = 0; i < 4; i++) {
                float4 v;
                v.x = fmaxf(acc[i][0] + sb1[c4 + 0], 0.f);
                v.y = fmaxf(acc[i][1] + sb1[c4 + 1], 0.f);
                v.z = fmaxf(acc[i][2] + sb1[c4 + 2], 0.f);
                v.w = fmaxf(acc[i][3] + sb1[c4 + 3], 0.f);
                *(float4*)(sH1 + (r4 + i) * HS + c4) = v;
            }
        }
        __syncthreads();

        // L2: [64,64]@[64,64] -> sH2
        {
            float acc[4][4] = {};
            gemm44<HH, HH, HS>(sH1, sW2, r4, c4, acc);
            #pragma unroll
            for (int i = 0; i < 4; i++) {
                float4 v;
                v.x = fmaxf(acc[i][0] + sb2[c4 + 0], 0.f);
                v.y = fmaxf(acc[i][1] + sb2[c4 + 1], 0.f);
                v.z = fmaxf(acc[i][2] + sb2[c4 + 2], 0.f);
                v.w = fmaxf(acc[i][3] + sb2[c4 + 3], 0.f);
                *(float4*)(sH2 + (r4 + i) * HS + c4) = v;
            }
        }
        __syncthreads();

        // L3: [64,64]@[64,128] -> msg into sX (reuse)
        {
            float acc[8][4] = {};
            gemm84<HH, HS>(sH2, sW3, r8, c8, acc);
            #pragma unroll
            for (int i = 0; i < 8; i++) {
                float4 v;
                v.x = fmaxf(acc[i][0] + sb3[c8 + 0], 0.f);
                v.y = fmaxf(acc[i][1] + sb3[c8 + 1], 0.f);
                v.z = fmaxf(acc[i][2] + sb3[c8 + 2], 0.f);
                v.w = fmaxf(acc[i][3] + sb3[c8 + 3], 0.f);
                *(float4*)(sX + (r8 + i) * XS + c8) = v;
            }
        }
        __syncthreads();

        // L4 (fused node-layer-1 projection): [64,128]@[128,64] -> atomics
        {
            float acc[4][4] = {};
            gemm44<DD, HH, XS>(sX, sWn, r4, c4, acc);
            #pragma unroll
            for (int i = 0; i < 4; i++) {
                int dst = sDst[r4 + i];
                if (dst >= 0) {
                    float* p = g_acc + (long)dst * HH + c4;
                    atomicAdd(p + 0, acc[i][0]);
                    atomicAdd(p + 1, acc[i][1]);
                    atomicAdd(p + 2, acc[i][2]);
                    atomicAdd(p + 3, acc[i][3]);
                }
            }
        }
    }
}

// ---------------------------------------------------------------------------
// Node kernel: h = relu(relu(nf)@Wn1[0:D] + g_acc + bn1); h = relu(h@Wn2+bn2);
//              out = h@Wn3 + bn3
// ---------------------------------------------------------------------------
__global__ __launch_bounds__(NTHREADS, 1)
void node_kernel(const float* __restrict__ nf,
                 const float* __restrict__ Wn1, const float* __restrict__ bn1,
                 const float* __restrict__ Wn2, const float* __restrict__ bn2,
                 const float* __restrict__ Wn3, const float* __restrict__ bn3,
                 float* __restrict__ out) {
    extern __shared__ float sm[];
    float* sW1 = sm;                      // [128][64]
    float* sW2 = sW1 + DD * HH;           // [64][64]
    float* sW3 = sW2 + HH * HH;           // [64][128]
    float* sb1 = sW3 + HH * DD;
    float* sb2 = sb1 + HH;
    float* sb3 = sb2 + HH;
    float* sX  = sb3 + DD;                // [64][XS]
    float* sH1 = sX + TE * XS;            // [64][HS]
    float* sH2 = sH1 + TE * HS;           // [64][HS]

    const int t = threadIdx.x;
    for (int i = t; i < DD * HH / 4; i += NTHREADS) ((float4*)sW1)[i] = ((const float4*)Wn1)[i];
    for (int i = t; i < HH * HH / 4; i += NTHREADS) ((float4*)sW2)[i] = ((const float4*)Wn2)[i];
    for (int i = t; i < HH * DD / 4; i += NTHREADS) ((float4*)sW3)[i] = ((const float4*)Wn3)[i];
    if (t < HH) { sb1[t] = bn1[t]; sb2[t] = bn2[t]; }
    if (t < DD) sb3[t] = bn3[t];

    const int ntiles = (NN + TE - 1) / TE;
    const int c4 = (t & 15) * 4, r4 = (t >> 4) * 4;
    const int c8 = (t & 31) * 4, r8 = (t >> 5) * 8;
    const int grow = t >> 2, gj = t & 3;

    for (int tile = blockIdx.x; tile < ntiles; tile += gridDim.x) {
        __syncthreads();
        {
            const int n = tile * TE + grow;
            float* dr = sX + grow * XS;
            if (n < NN) {
                const float* xr = nf + (long)n * DD;
                #pragma unroll
                for (int i = 0; i < 8; i++) {
                    int d0 = gj * 4 + i * 16;
                    float4 v = *(const float4*)(xr + d0);
                    v.x = fmaxf(v.x, 0.f); v.y = fmaxf(v.y, 0.f);
                    v.z = fmaxf(v.z, 0.f); v.w = fmaxf(v.w, 0.f);
                    *(float4*)(dr + d0) = v;
                }
            } else {
                #pragma unroll
                for (int i = 0; i < 8; i++) {
                    int d0 = gj * 4 + i * 16;
                    *(float4*)(dr + d0) = make_float4(0.f, 0.f, 0.f, 0.f);
                }
            }
        }
        __syncthreads();

        // L1 + aggregate + bias
        {
            float acc[4][4] = {};
            gemm44<DD, HH, XS>(sX, sW1, r4, c4, acc);
            #pragma unroll
            for (int i = 0; i < 4; i++) {
                int n = tile * TE + r4 + i;
                float4 v = make_float4(0.f, 0.f, 0.f, 0.f);
                if (n < NN) {
                    float4 ga = *(const float4*)(g_acc + (long)n * HH + c4);
                    v.x = fmaxf(acc[i][0] + ga.x + sb1[c4 + 0], 0.f);
                    v.y = fmaxf(acc[i][1] + ga.y + sb1[c4 + 1], 0.f);
                    v.z = fmaxf(acc[i][2] + ga.z + sb1[c4 + 2], 0.f);
                    v.w = fmaxf(acc[i][3] + ga.w + sb1[c4 + 3], 0.f);
                }
                *(float4*)(sH1 + (r4 + i) * HS + c4) = v;
            }
        }
        __syncthreads();

        // L2
        {
            float acc[4][4] = {};
            gemm44<HH, HH, HS>(sH1, sW2, r4, c4, acc);
            #pragma unroll
            for (int i = 0; i < 4; i++) {
                float4 v;
                v.x = fmaxf(acc[i][0] + sb2[c4 + 0], 0.f);
                v.y = fmaxf(acc[i][1] + sb2[c4 + 1], 0.f);
                v.z = fmaxf(acc[i][2] + sb2[c4 + 2], 0.f);
                v.w = fmaxf(acc[i][3] + sb2[c4 + 3], 0.f);
                *(float4*)(sH2 + (r4 + i) * HS + c4) = v;
            }
        }
        __syncthreads();

        // L3 -> out
        {
            float acc[8][4] = {};
            gemm84<HH, HS>(sH2, sW3, r8, c8, acc);
            #pragma unroll
            for (int i = 0; i < 8; i++) {
                int n = tile * TE + r8 + i;
                if (n < NN) {
                    float4 v;
                    v.x = acc[i][0] + sb3[c8 + 0];
                    v.y = acc[i][1] + sb3[c8 + 1];
                    v.z = acc[i][2] + sb3[c8 + 2];
                    v.w = acc[i][3] + sb3[c8 + 3];
                    *(float4*)(out + (long)n * DD + c8) = v;
                }
            }
        }
    }
}

extern "C" void kernel_launch(void* const* d_in, const int* in_sizes, int n_in,
                              void* d_out, int out_size) {
    const float* nf   = (const float*)d_in[0];
    const int*   esrc = (const int*)d_in[1];
    const int*   edst = (const int*)d_in[2];
    const int*   etyp = (const int*)d_in[3];
    const float* Wr1  = (const float*)d_in[4];
    const float* br1  = (const float*)d_in[5];
    const float* Wr2  = (const float*)d_in[6];
    const float* br2  = (const float*)d_in[7];
    const float* Wr3  = (const float*)d_in[8];
    const float* br3  = (const float*)d_in[9];
    const float* Wn1  = (const float*)d_in[10];
    const float* bn1  = (const float*)d_in[11];
    const float* Wn2  = (const float*)d_in[12];
    const float* bn2  = (const float*)d_in[13];
    const float* Wn3  = (const float*)d_in[14];
    const float* bn3  = (const float*)d_in[15];
    float* out = (float*)d_out;

    const int EDGE_SMEM = (DD*HH + HH*HH + HH*DD + DD*HH + HH + HH + DD
                           + TE*XS + 2*TE*HS) * 4 + 2 * TE * 4;
    const int NODE_SMEM = (DD*HH + HH*HH + HH*DD + HH + HH + DD
                           + TE*XS + 2*TE*HS) * 4;

    cudaFuncSetAttribute(edge_kernel, cudaFuncAttributeMaxDynamicSharedMemorySize, EDGE_SMEM);
    cudaFuncSetAttribute(node_kernel, cudaFuncAttributeMaxDynamicSharedMemorySize, NODE_SMEM);

    zero_kernel<<<(NN * HH / 4 + NTHREADS - 1) / NTHREADS, NTHREADS>>>();
    bin_kernel<<<(NE + NTHREADS - 1) / NTHREADS, NTHREADS>>>(etyp);
    edge_kernel<<<NSM, NTHREADS, EDGE_SMEM>>>(nf, esrc, edst,
                                              Wr1, br1, Wr2, br2, Wr3, br3, Wn1);
    node_kernel<<<NSM, NTHREADS, NODE_SMEM>>>(nf, Wn1, bn1, Wn2, bn2, Wn3, bn3, out);
}

// round 4
// speedup vs baseline: 11.3958x; 2.2262x over previous
#include <cuda_runtime.h>
#include <cstdint>

#define NN 50000
#define NE 200000
#define DD 128
#define RR 4
#define HH 64
#define TE 64            // rows (edges/nodes) per tile (M)
#define XS 132           // stride for 128-wide act buffers (4 mod 32)
#define HS 68            // stride for 64-wide act buffers  (4 mod 32)
#define NTHREADS 256
#define NSM 152

__device__ float g_acc[NN * HH];
__device__ int   g_bucket[RR * NE];
__device__ int   g_cnt[RR];

__global__ void zero_kernel() {
    int i = blockIdx.x * blockDim.x + threadIdx.x;
    if (i < NN * HH / 4) ((float4*)g_acc)[i] = make_float4(0.f, 0.f, 0.f, 0.f);
    if (i < RR) g_cnt[i] = 0;
}

__global__ void bin_kernel(const int* __restrict__ etype) {
    __shared__ int s_cnt[RR];
    __shared__ int s_base[RR];
    int t = threadIdx.x;
    if (t < RR) s_cnt[t] = 0;
    __syncthreads();
    int e = blockIdx.x * blockDim.x + t;
    int r = -1, pos = 0;
    if (e < NE) { r = etype[e]; pos = atomicAdd(&s_cnt[r], 1); }
    __syncthreads();
    if (t < RR) s_base[t] = atomicAdd(&g_cnt[t], s_cnt[t]);
    __syncthreads();
    if (r >= 0) g_bucket[r * NE + s_base[r] + pos] = e;
}

// ---- tf32 helpers -----------------------------------------------------------
__device__ __forceinline__ uint32_t f2tf(float x) {
    uint32_t u;
    asm("cvt.rna.tf32.f32 %0, %1;" : "=r"(u) : "f"(x));
    return u;
}
__device__ __forceinline__ float tfbits(float x) {       // rounded bits as float
    return __uint_as_float(f2tf(x));
}
__device__ __forceinline__ float tfrelu(float x) {
    return __uint_as_float(f2tf(fmaxf(x, 0.f)));
}
__device__ __forceinline__ void mma_tf32(float c[4], uint32_t a0, uint32_t a1,
                                         uint32_t a2, uint32_t a3,
                                         uint32_t b0, uint32_t b1) {
    asm volatile(
        "mma.sync.aligned.m16n8k8.row.col.f32.tf32.tf32.f32 "
        "{%0,%1,%2,%3}, {%4,%5,%6,%7}, {%8,%9}, {%0,%1,%2,%3};"
        : "+f"(c[0]), "+f"(c[1]), "+f"(c[2]), "+f"(c[3])
        : "r"(a0), "r"(a1), "r"(a2), "r"(a3), "r"(b0), "r"(b1));
}
__device__ __forceinline__ void red2(float* p, float x, float y) {
    asm volatile("red.global.add.v2.f32 [%0], {%1, %2};"
                 :: "l"(p), "f"(x), "f"(y) : "memory");
}

// Warp GEMM: C[16·?, 8·NCH] over K. act: [M][AST] tf32-bits, wT: [N][KS] tf32-bits.
// Warp covers rows mrow0..mrow0+15, cols ncol0..ncol0+8*NCH-1.
template<int K, int AST, int KS, int NCH>
__device__ __forceinline__ void wgemm(const float* __restrict__ act,
                                      const float* __restrict__ wT,
                                      int mrow0, int ncol0, int g, int tig,
                                      float c[NCH][4]) {
    const float* ar0 = act + (mrow0 + g) * AST + tig;
    const float* ar1 = act + (mrow0 + g + 8) * AST + tig;
    #pragma unroll
    for (int k0 = 0; k0 < K; k0 += 8) {
        uint32_t a0 = __float_as_uint(ar0[k0]);
        uint32_t a1 = __float_as_uint(ar1[k0]);
        uint32_t a2 = __float_as_uint(ar0[k0 + 4]);
        uint32_t a3 = __float_as_uint(ar1[k0 + 4]);
        #pragma unroll
        for (int j = 0; j < NCH; j++) {
            const float* wn = wT + (ncol0 + j * 8 + g) * KS + k0 + tig;
            uint32_t b0 = __float_as_uint(wn[0]);
            uint32_t b1 = __float_as_uint(wn[4]);
            mma_tf32(c[j], a0, a1, a2, a3, b0, b1);
        }
    }
}

// Epilogue: bias + relu + tf32-round, store to smem [M][OST].
template<int NCH>
__device__ __forceinline__ void epi_store(float c[NCH][4], float* outb, int OST,
                                          const float* bias, int mrow0, int ncol0,
                                          int g, int tig) {
    #pragma unroll
    for (int j = 0; j < NCH; j++) {
        int col = ncol0 + j * 8 + 2 * tig;
        float b0 = bias[col], b1 = bias[col + 1];
        float* o0 = outb + (mrow0 + g) * OST + col;
        float* o1 = outb + (mrow0 + g + 8) * OST + col;
        o0[0] = tfrelu(c[j][0] + b0); o0[1] = tfrelu(c[j][1] + b1);
        o1[0] = tfrelu(c[j][2] + b0); o1[1] = tfrelu(c[j][3] + b1);
    }
}

// ---------------------------------------------------------------------------
// Edge kernel (tensor-core): per edge of relation r:
//   h1=relu(x@W1+b1); h2=relu(h1@W2+b2); msg=relu(h2@W3+b3);
//   p=msg@Wn1[(1+r)D:(2+r)D];  g_acc[dst] += p
// ---------------------------------------------------------------------------
__global__ __launch_bounds__(NTHREADS, 1)
void edge_kernel(const float* __restrict__ nf,
                 const int* __restrict__ esrc, const int* __restrict__ edst,
                 const float* __restrict__ Wr1, const float* __restrict__ br1,
                 const float* __restrict__ Wr2, const float* __restrict__ br2,
                 const float* __restrict__ Wr3, const float* __restrict__ br3,
                 const float* __restrict__ Wn1) {
    extern __shared__ float sm[];
    float* sW1T = sm;                       // [64][132]  (W1^T, tf32)
    float* sW2T = sW1T + HH * XS;           // [64][68]
    float* sW3T = sW2T + HH * HS;           // [128][68]
    float* sWnT = sW3T + DD * HS;           // [64][132]
    float* sb1  = sWnT + HH * XS;           // 64
    float* sb2  = sb1 + HH;                 // 64
    float* sb3  = sb2 + HH;                 // 128
    float* sX   = sb3 + DD;                 // [64][132]  x / msg (tf32 bits)
    float* sH1  = sX + TE * XS;             // [64][68]
    float* sH2  = sH1 + TE * HS;            // [64][68]
    int*  sSrc  = (int*)(sH2 + TE * HS);    // 64
    int*  sDst  = sSrc + TE;                // 64

    const int t     = threadIdx.x;
    const int rel   = blockIdx.x & (RR - 1);
    const int bslot = blockIdx.x >> 2;
    const int nb    = gridDim.x >> 2;

    // Load weights transposed + tf32-rounded
    const float* gW1 = Wr1 + rel * DD * HH;
    const float* gW2 = Wr2 + rel * HH * HH;
    const float* gW3 = Wr3 + rel * HH * DD;
    const float* gWn = Wn1 + (1 + rel) * DD * HH;
    for (int i = t; i < DD * HH; i += NTHREADS) {
        int d = i >> 6, h = i & 63;
        sW1T[h * XS + d] = tfbits(gW1[i]);
        sWnT[h * XS + d] = tfbits(gWn[i]);
    }
    for (int i = t; i < HH * HH; i += NTHREADS) {
        int k = i >> 6, h = i & 63;
        sW2T[h * HS + k] = tfbits(gW2[i]);
    }
    for (int i = t; i < HH * DD; i += NTHREADS) {
        int k = i >> 7, d = i & 127;
        sW3T[d * HS + k] = tfbits(gW3[i]);
    }
    if (t < HH) { sb1[t] = br1[rel * HH + t]; sb2[t] = br2[rel * HH + t]; }
    if (t < DD) { sb3[t] = br3[rel * DD + t]; }

    const int cnt    = g_cnt[rel];
    const int ntiles = (cnt + TE - 1) / TE;

    const int lane = t & 31, w = t >> 5;
    const int g = lane >> 2, tig = lane & 3;
    const int mrow = (w & 3) * 16;          // warp's 16-row block
    const int nc4  = (w >> 2) * 32;         // 64-col layers: 4 n-chunks
    const int nc8  = (w >> 2) * 64;         // 128-col layer: 8 n-chunks
    const int grow = t >> 2, gj = t & 3;    // gather map

    for (int tile = bslot; tile < ntiles; tile += nb) {
        __syncthreads();
        if (t < TE) {
            int idx = tile * TE + t;
            if (idx < cnt) {
                int e = g_bucket[rel * NE + idx];
                sSrc[t] = esrc[e];
                sDst[t] = edst[e];
            } else { sSrc[t] = 0; sDst[t] = -1; }
        }
        __syncthreads();

        // Gather x_src tile (tf32-rounded)
        {
            const float* xr = nf + (long)sSrc[grow] * DD;
            float* dr = sX + grow * XS;
            #pragma unroll
            for (int i = 0; i < 8; i++) {
                int d0 = gj * 4 + i * 16;
                float4 v = *(const float4*)(xr + d0);
                dr[d0 + 0] = tfbits(v.x); dr[d0 + 1] = tfbits(v.y);
                dr[d0 + 2] = tfbits(v.z); dr[d0 + 3] = tfbits(v.w);
            }
        }
        __syncthreads();

        // L1: [64,128]@[128,64]
        {
            float c[4][4] = {};
            wgemm<DD, XS, XS, 4>(sX, sW1T, mrow, nc4, g, tig, c);
            epi_store<4>(c, sH1, HS, sb1, mrow, nc4, g, tig);
        }
        __syncthreads();

        // L2: [64,64]@[64,64]
        {
            float c[4][4] = {};
            wgemm<HH, HS, HS, 4>(sH1, sW2T, mrow, nc4, g, tig, c);
            epi_store<4>(c, sH2, HS, sb2, mrow, nc4, g, tig);
        }
        __syncthreads();

        // L3: [64,64]@[64,128] -> msg into sX
        {
            float c[8][4] = {};
            wgemm<HH, HS, HS, 8>(sH2, sW3T, mrow, nc8, g, tig, c);
            epi_store<8>(c, sX, XS, sb3, mrow, nc8, g, tig);
        }
        __syncthreads();

        // L4: [64,128]@[128,64] -> vectorized reductions into g_acc
        {
            float c[4][4] = {};
            wgemm<DD, XS, XS, 4>(sX, sWnT, mrow, nc4, g, tig, c);
            int d0 = sDst[mrow + g];
            int d1 = sDst[mrow + g + 8];
            #pragma unroll
            for (int j = 0; j < 4; j++) {
                int col = nc4 + j * 8 + 2 * tig;
                if (d0 >= 0) red2(g_acc + (long)d0 * HH + col, c[j][0], c[j][1]);
                if (d1 >= 0) red2(g_acc + (long)d1 * HH + col, c[j][2], c[j][3]);
            }
        }
    }
}

// ---------------------------------------------------------------------------
// Node kernel (tensor-core): h=relu(relu(nf)@Wn1[0:D]+g_acc+bn1);
//                            h=relu(h@Wn2+bn2); out=h@Wn3+bn3
// ---------------------------------------------------------------------------
__global__ __launch_bounds__(NTHREADS, 1)
void node_kernel(const float* __restrict__ nf,
                 const float* __restrict__ Wn1, const float* __restrict__ bn1,
                 const float* __restrict__ Wn2, const float* __restrict__ bn2,
                 const float* __restrict__ Wn3, const float* __restrict__ bn3,
                 float* __restrict__ out) {
    extern __shared__ float sm[];
    float* sW1T = sm;                       // [64][132]
    float* sW2T = sW1T + HH * XS;           // [64][68]
    float* sW3T = sW2T + HH * HS;           // [128][68]
    float* sb1  = sW3T + DD * HS;
    float* sb2  = sb1 + HH;
    float* sb3  = sb2 + HH;
    float* sX   = sb3 + DD;                 // [64][132]
    float* sH1  = sX + TE * XS;             // [64][68]
    float* sH2  = sH1 + TE * HS;            // [64][68]

    const int t = threadIdx.x;
    for (int i = t; i < DD * HH; i += NTHREADS) {
        int d = i >> 6, h = i & 63;
        sW1T[h * XS + d] = tfbits(Wn1[i]);
    }
    for (int i = t; i < HH * HH; i += NTHREADS) {
        int k = i >> 6, h = i & 63;
        sW2T[h * HS + k] = tfbits(Wn2[i]);
    }
    for (int i = t; i < HH * DD; i += NTHREADS) {
        int k = i >> 7, d = i & 127;
        sW3T[d * HS + k] = tfbits(Wn3[i]);
    }
    if (t < HH) { sb1[t] = bn1[t]; sb2[t] = bn2[t]; }
    if (t < DD) sb3[t] = bn3[t];

    const int ntiles = (NN + TE - 1) / TE;
    const int lane = t & 31, w = t >> 5;
    const int g = lane >> 2, tig = lane & 3;
    const int mrow = (w & 3) * 16;
    const int nc4  = (w >> 2) * 32;
    const int nc8  = (w >> 2) * 64;
    const int grow = t >> 2, gj = t & 3;

    for (int tile = blockIdx.x; tile < ntiles; tile += gridDim.x) {
        const int base = tile * TE;
        __syncthreads();
        {
            const int n = base + grow;
            float* dr = sX + grow * XS;
            if (n < NN) {
                const float* xr = nf + (long)n * DD;
                #pragma unroll
                for (int i = 0; i < 8; i++) {
                    int d0 = gj * 4 + i * 16;
                    float4 v = *(const float4*)(xr + d0);
                    dr[d0 + 0] = tfrelu(v.x); dr[d0 + 1] = tfrelu(v.y);
                    dr[d0 + 2] = tfrelu(v.z); dr[d0 + 3] = tfrelu(v.w);
                }
            } else {
                #pragma unroll
                for (int i = 0; i < 8; i++) {
                    int d0 = gj * 4 + i * 16;
                    *(float4*)(dr + d0) = make_float4(0.f, 0.f, 0.f, 0.f);
                }
            }
        }
        __syncthreads();

        // L1 + g_acc + bias
        {
            float c[4][4] = {};
            wgemm<DD, XS, XS, 4>(sX, sW1T, mrow, nc4, g, tig, c);
            int n0 = base + mrow + g;
            int n1 = n0 + 8;
            #pragma unroll
            for (int j = 0; j < 4; j++) {
                int col = nc4 + j * 8 + 2 * tig;
                float b0 = sb1[col], b1 = sb1[col + 1];
                float* o0 = sH1 + (mrow + g) * HS + col;
                float* o1 = sH1 + (mrow + g + 8) * HS + col;
                if (n0 < NN) {
                    float2 ga = *(const float2*)(g_acc + (long)n0 * HH + col);
                    o0[0] = tfrelu(c[j][0] + ga.x + b0);
                    o0[1] = tfrelu(c[j][1] + ga.y + b1);
                } else { o0[0] = 0.f; o0[1] = 0.f; }
                if (n1 < NN) {
                    float2 ga = *(const float2*)(g_acc + (long)n1 * HH + col);
                    o1[0] = tfrelu(c[j][2] + ga.x + b0);
                    o1[1] = tfrelu(c[j][3] + ga.y + b1);
                } else { o1[0] = 0.f; o1[1] = 0.f; }
            }
        }
        __syncthreads();

        // L2
        {
            float c[4][4] = {};
            wgemm<HH, HS, HS, 4>(sH1, sW2T, mrow, nc4, g, tig, c);
            epi_store<4>(c, sH2, HS, sb2, mrow, nc4, g, tig);
        }
        __syncthreads();

        // L3 -> out (fp32, no rounding)
        {
            float c[8][4] = {};
            wgemm<HH, HS, HS, 8>(sH2, sW3T, mrow, nc8, g, tig, c);
            int n0 = base + mrow + g;
            int n1 = n0 + 8;
            #pragma unroll
            for (int j = 0; j < 8; j++) {
                int col = nc8 + j * 8 + 2 * tig;
                float b0 = sb3[col], b1 = sb3[col + 1];
                if (n0 < NN) {
                    float2 v; v.x = c[j][0] + b0; v.y = c[j][1] + b1;
                    *(float2*)(out + (long)n0 * DD + col) = v;
                }
                if (n1 < NN) {
                    float2 v; v.x = c[j][2] + b0; v.y = c[j][3] + b1;
                    *(float2*)(out + (long)n1 * DD + col) = v;
                }
            }
        }
    }
}

extern "C" void kernel_launch(void* const* d_in, const int* in_sizes, int n_in,
                              void* d_out, int out_size) {
    const float* nf   = (const float*)d_in[0];
    const int*   esrc = (const int*)d_in[1];
    const int*   edst = (const int*)d_in[2];
    const int*   etyp = (const int*)d_in[3];
    const float* Wr1  = (const float*)d_in[4];
    const float* br1  = (const float*)d_in[5];
    const float* Wr2  = (const float*)d_in[6];
    const float* br2  = (const float*)d_in[7];
    const float* Wr3  = (const float*)d_in[8];
    const float* br3  = (const float*)d_in[9];
    const float* Wn1  = (const float*)d_in[10];
    const float* bn1  = (const float*)d_in[11];
    const float* Wn2  = (const float*)d_in[12];
    const float* bn2  = (const float*)d_in[13];
    const float* Wn3  = (const float*)d_in[14];
    const float* bn3  = (const float*)d_in[15];
    float* out = (float*)d_out;

    const int EDGE_SMEM = (HH*XS + HH*HS + DD*HS + HH*XS + HH + HH + DD
                           + TE*XS + 2*TE*HS) * 4 + 2 * TE * 4;
    const int NODE_SMEM = (HH*XS + HH*HS + DD*HS + HH + HH + DD
                           + TE*XS + 2*TE*HS) * 4;

    cudaFuncSetAttribute(edge_kernel, cudaFuncAttributeMaxDynamicSharedMemorySize, EDGE_SMEM);
    cudaFuncSetAttribute(node_kernel, cudaFuncAttributeMaxDynamicSharedMemorySize, NODE_SMEM);

    zero_kernel<<<(NN * HH / 4 + NTHREADS - 1) / NTHREADS, NTHREADS>>>();
    bin_kernel<<<(NE + NTHREADS - 1) / NTHREADS, NTHREADS>>>(etyp);
    edge_kernel<<<NSM, NTHREADS, EDGE_SMEM>>>(nf, esrc, edst,
                                              Wr1, br1, Wr2, br2, Wr3, br3, Wn1);
    node_kernel<<<NSM, NTHREADS, NODE_SMEM>>>(nf, Wn1, bn1, Wn2, bn2, Wn3, bn3, out);
}

// round 5
// speedup vs baseline: 18.8547x; 1.6545x over previous
#include <cuda_runtime.h>
#include <cuda_fp16.h>
#include <cstdint>

#define NN 50000
#define NE 200000
#define DD 128
#define RR 4
#define HH 64
#define TE 64            // rows (edges/nodes) per tile (M)
#define XSH 136          // stride (halves) for 128-wide act/weight buffers; /2 = 68 ≡ 4 mod 32
#define HSH 72           // stride (halves) for 64-wide buffers;              /2 = 36 ≡ 4 mod 32
#define NTHREADS 256
#define NSM 152

__device__ float g_acc[NN * HH];
__device__ int   g_bucket[RR * NE];
__device__ int   g_cnt[RR];

__global__ void zero_kernel() {
    int i = blockIdx.x * blockDim.x + threadIdx.x;
    if (i < NN * HH / 4) ((float4*)g_acc)[i] = make_float4(0.f, 0.f, 0.f, 0.f);
    if (i < RR) g_cnt[i] = 0;
}

__global__ void bin_kernel(const int* __restrict__ etype) {
    __shared__ int s_cnt[RR];
    __shared__ int s_base[RR];
    int t = threadIdx.x;
    if (t < RR) s_cnt[t] = 0;
    __syncthreads();
    int e = blockIdx.x * blockDim.x + t;
    int r = -1, pos = 0;
    if (e < NE) { r = etype[e]; pos = atomicAdd(&s_cnt[r], 1); }
    __syncthreads();
    if (t < RR) s_base[t] = atomicAdd(&g_cnt[t], s_cnt[t]);
    __syncthreads();
    if (r >= 0) g_bucket[r * NE + s_base[r] + pos] = e;
}

// ---- fp16 MMA helpers -------------------------------------------------------
__device__ __forceinline__ void mma_f16(float c[4], uint32_t a0, uint32_t a1,
                                        uint32_t a2, uint32_t a3,
                                        uint32_t b0, uint32_t b1) {
    asm volatile(
        "mma.sync.aligned.m16n8k16.row.col.f32.f16.f16.f32 "
        "{%0,%1,%2,%3}, {%4,%5,%6,%7}, {%8,%9}, {%0,%1,%2,%3};"
        : "+f"(c[0]), "+f"(c[1]), "+f"(c[2]), "+f"(c[3])
        : "r"(a0), "r"(a1), "r"(a2), "r"(a3), "r"(b0), "r"(b1));
}
__device__ __forceinline__ void red2(float* p, float x, float y) {
    asm volatile("red.global.add.v2.f32 [%0], {%1, %2};"
                 :: "l"(p), "f"(x), "f"(y) : "memory");
}

// Warp GEMM over K (fp16 in, fp32 acc). act: [M][AST] halves, wT: [N][KS] halves.
// Warp covers rows mrow0..+15, cols ncol0..+8*NCH-1.
// C frag: c[j][0]=[g][col], c[j][1]=[g][col+1], c[j][2]=[g+8][col], c[j][3]=[g+8][col+1],
// col = ncol0 + j*8 + 2*tig.
template<int K, int AST, int KS, int NCH>
__device__ __forceinline__ void wgemm(const __half* __restrict__ act,
                                      const __half* __restrict__ wT,
                                      int mrow0, int ncol0, int g, int tig,
                                      float c[NCH][4]) {
    const __half* ar0 = act + (mrow0 + g) * AST + 2 * tig;
    const __half* ar1 = ar0 + 8 * AST;
    #pragma unroll
    for (int k0 = 0; k0 < K; k0 += 16) {
        uint32_t a0 = *(const uint32_t*)(ar0 + k0);
        uint32_t a1 = *(const uint32_t*)(ar1 + k0);
        uint32_t a2 = *(const uint32_t*)(ar0 + k0 + 8);
        uint32_t a3 = *(const uint32_t*)(ar1 + k0 + 8);
        #pragma unroll
        for (int j = 0; j < NCH; j++) {
            const __half* wn = wT + (ncol0 + j * 8 + g) * KS + k0 + 2 * tig;
            uint32_t b0 = *(const uint32_t*)(wn);
            uint32_t b1 = *(const uint32_t*)(wn + 8);
            mma_f16(c[j], a0, a1, a2, a3, b0, b1);
        }
    }
}

// Epilogue: bias + relu + fp16-round, store half2 to smem [M][OST].
template<int NCH>
__device__ __forceinline__ void epi_store(float c[NCH][4], __half* outb, int OST,
                                          const float* bias, int mrow0, int ncol0,
                                          int g, int tig) {
    #pragma unroll
    for (int j = 0; j < NCH; j++) {
        int col = ncol0 + j * 8 + 2 * tig;
        float b0 = bias[col], b1 = bias[col + 1];
        *(half2*)(outb + (mrow0 + g) * OST + col) =
            __floats2half2_rn(fmaxf(c[j][0] + b0, 0.f), fmaxf(c[j][1] + b1, 0.f));
        *(half2*)(outb + (mrow0 + g + 8) * OST + col) =
            __floats2half2_rn(fmaxf(c[j][2] + b0, 0.f), fmaxf(c[j][3] + b1, 0.f));
    }
}

// SMEM layouts (byte offsets)
#define E_W1T 0
#define E_W2T (E_W1T + HH * XSH * 2)      // 17408
#define E_W3T (E_W2T + HH * HSH * 2)      // + 9216
#define E_WNT (E_W3T + DD * HSH * 2)      // + 18432
#define E_SX  (E_WNT + HH * XSH * 2)      // + 17408
#define E_SH1 (E_SX + TE * XSH * 2)       // + 17408
#define E_SH2 (E_SH1 + TE * HSH * 2)      // + 9216
#define E_SB1 (E_SH2 + TE * HSH * 2)      // + 9216
#define E_SB2 (E_SB1 + HH * 4)
#define E_SB3 (E_SB2 + HH * 4)
#define E_SRC (E_SB3 + DD * 4)
#define E_DST (E_SRC + TE * 4)
#define E_TOTAL (E_DST + TE * 4)          // 99840 B

#define N_W1T 0
#define N_W2T (N_W1T + HH * XSH * 2)
#define N_W3T (N_W2T + HH * HSH * 2)
#define N_SX  (N_W3T + DD * HSH * 2)
#define N_SH1 (N_SX + TE * XSH * 2)
#define N_SH2 (N_SH1 + TE * HSH * 2)
#define N_SB1 (N_SH2 + TE * HSH * 2)
#define N_SB2 (N_SB1 + HH * 4)
#define N_SB3 (N_SB2 + HH * 4)
#define N_TOTAL (N_SB3 + DD * 4)          // 81920 B

// ---------------------------------------------------------------------------
// Edge kernel: per edge of relation r:
//   h1=relu(x@W1+b1); h2=relu(h1@W2+b2); msg=relu(h2@W3+b3);
//   p=msg@Wn1[(1+r)D:(2+r)D];  g_acc[dst] += p
// ---------------------------------------------------------------------------
__global__ __launch_bounds__(NTHREADS, 2)
void edge_kernel(const float* __restrict__ nf,
                 const int* __restrict__ esrc, const int* __restrict__ edst,
                 const float* __restrict__ Wr1, const float* __restrict__ br1,
                 const float* __restrict__ Wr2, const float* __restrict__ br2,
                 const float* __restrict__ Wr3, const float* __restrict__ br3,
                 const float* __restrict__ Wn1) {
    extern __shared__ __align__(16) char smraw[];
    __half* sW1T = (__half*)(smraw + E_W1T);   // [64][XSH]  W1^T
    __half* sW2T = (__half*)(smraw + E_W2T);   // [64][HSH]
    __half* sW3T = (__half*)(smraw + E_W3T);   // [128][HSH]
    __half* sWnT = (__half*)(smraw + E_WNT);   // [64][XSH]
    __half* sX   = (__half*)(smraw + E_SX);    // [64][XSH]  x / msg
    __half* sH1  = (__half*)(smraw + E_SH1);   // [64][HSH]
    __half* sH2  = (__half*)(smraw + E_SH2);   // [64][HSH]
    float*  sb1  = (float*)(smraw + E_SB1);
    float*  sb2  = (float*)(smraw + E_SB2);
    float*  sb3  = (float*)(smraw + E_SB3);
    int*    sSrc = (int*)(smraw + E_SRC);
    int*    sDst = (int*)(smraw + E_DST);

    const int t     = threadIdx.x;
    const int rel   = blockIdx.x & (RR - 1);
    const int bslot = blockIdx.x >> 2;
    const int nb    = gridDim.x >> 2;

    const float* gW1 = Wr1 + rel * DD * HH;
    const float* gW2 = Wr2 + rel * HH * HH;
    const float* gW3 = Wr3 + rel * HH * DD;
    const float* gWn = Wn1 + (1 + rel) * DD * HH;
    for (int i = t; i < DD * HH; i += NTHREADS) {
        int d = i >> 6, h = i & 63;
        sW1T[h * XSH + d] = __float2half(gW1[i]);
        sWnT[h * XSH + d] = __float2half(gWn[i]);
    }
    for (int i = t; i < HH * HH; i += NTHREADS) {
        int k = i >> 6, h = i & 63;
        sW2T[h * HSH + k] = __float2half(gW2[i]);
    }
    for (int i = t; i < HH * DD; i += NTHREADS) {
        int k = i >> 7, d = i & 127;
        sW3T[d * HSH + k] = __float2half(gW3[i]);
    }
    if (t < HH) { sb1[t] = br1[rel * HH + t]; sb2[t] = br2[rel * HH + t]; }
    if (t < DD) { sb3[t] = br3[rel * DD + t]; }

    const int cnt    = g_cnt[rel];
    const int ntiles = (cnt + TE - 1) / TE;

    const int lane = t & 31, w = t >> 5;
    const int g = lane >> 2, tig = lane & 3;
    const int mrow = (w & 3) * 16;
    const int nc4  = (w >> 2) * 32;
    const int nc8  = (w >> 2) * 64;
    const int grow = t >> 2, gj = t & 3;

    for (int tile = bslot; tile < ntiles; tile += nb) {
        __syncthreads();
        if (t < TE) {
            int idx = tile * TE + t;
            if (idx < cnt) {
                int e = g_bucket[rel * NE + idx];
                sSrc[t] = esrc[e];
                sDst[t] = edst[e];
            } else { sSrc[t] = 0; sDst[t] = -1; }
        }
        __syncthreads();

        // Gather x_src tile -> fp16
        {
            const float* xr = nf + (long)sSrc[grow] * DD;
            __half* dr = sX + grow * XSH;
            #pragma unroll
            for (int i = 0; i < 8; i++) {
                int d0 = gj * 4 + i * 16;
                float4 v = *(const float4*)(xr + d0);
                *(half2*)(dr + d0)     = __floats2half2_rn(v.x, v.y);
                *(half2*)(dr + d0 + 2) = __floats2half2_rn(v.z, v.w);
            }
        }
        __syncthreads();

        // L1: [64,128]@[128,64]
        {
            float c[4][4] = {};
            wgemm<DD, XSH, XSH, 4>(sX, sW1T, mrow, nc4, g, tig, c);
            epi_store<4>(c, sH1, HSH, sb1, mrow, nc4, g, tig);
        }
        __syncthreads();

        // L2: [64,64]@[64,64]
        {
            float c[4][4] = {};
            wgemm<HH, HSH, HSH, 4>(sH1, sW2T, mrow, nc4, g, tig, c);
            epi_store<4>(c, sH2, HSH, sb2, mrow, nc4, g, tig);
        }
        __syncthreads();

        // L3: [64,64]@[64,128] -> msg into sX
        {
            float c[8][4] = {};
            wgemm<HH, HSH, HSH, 8>(sH2, sW3T, mrow, nc8, g, tig, c);
            epi_store<8>(c, sX, XSH, sb3, mrow, nc8, g, tig);
        }
        __syncthreads();

        // L4: [64,128]@[128,64] -> vectorized reductions into g_acc
        {
            float c[4][4] = {};
            wgemm<DD, XSH, XSH, 4>(sX, sWnT, mrow, nc4, g, tig, c);
            int d0 = sDst[mrow + g];
            int d1 = sDst[mrow + g + 8];
            #pragma unroll
            for (int j = 0; j < 4; j++) {
                int col = nc4 + j * 8 + 2 * tig;
                if (d0 >= 0) red2(g_acc + (long)d0 * HH + col, c[j][0], c[j][1]);
                if (d1 >= 0) red2(g_acc + (long)d1 * HH + col, c[j][2], c[j][3]);
            }
        }
    }
}

// ---------------------------------------------------------------------------
// Node kernel: h=relu(relu(nf)@Wn1[0:D]+g_acc+bn1); h=relu(h@Wn2+bn2);
//              out=h@Wn3+bn3
// ---------------------------------------------------------------------------
__global__ __launch_bounds__(NTHREADS, 2)
void node_kernel(const float* __restrict__ nf,
                 const float* __restrict__ Wn1, const float* __restrict__ bn1,
                 const float* __restrict__ Wn2, const float* __restrict__ bn2,
                 const float* __restrict__ Wn3, const float* __restrict__ bn3,
                 float* __restrict__ out) {
    extern __shared__ __align__(16) char smraw[];
    __half* sW1T = (__half*)(smraw + N_W1T);
    __half* sW2T = (__half*)(smraw + N_W2T);
    __half* sW3T = (__half*)(smraw + N_W3T);
    __half* sX   = (__half*)(smraw + N_SX);
    __half* sH1  = (__half*)(smraw + N_SH1);
    __half* sH2  = (__half*)(smraw + N_SH2);
    float*  sb1  = (float*)(smraw + N_SB1);
    float*  sb2  = (float*)(smraw + N_SB2);
    float*  sb3  = (float*)(smraw + N_SB3);

    const int t = threadIdx.x;
    for (int i = t; i < DD * HH; i += NTHREADS) {
        int d = i >> 6, h = i & 63;
        sW1T[h * XSH + d] = __float2half(Wn1[i]);
    }
    for (int i = t; i < HH * HH; i += NTHREADS) {
        int k = i >> 6, h = i & 63;
        sW2T[h * HSH + k] = __float2half(Wn2[i]);
    }
    for (int i = t; i < HH * DD; i += NTHREADS) {
        int k = i >> 7, d = i & 127;
        sW3T[d * HSH + k] = __float2half(Wn3[i]);
    }
    if (t < HH) { sb1[t] = bn1[t]; sb2[t] = bn2[t]; }
    if (t < DD) sb3[t] = bn3[t];

    const int ntiles = (NN + TE - 1) / TE;
    const int lane = t & 31, w = t >> 5;
    const int g = lane >> 2, tig = lane & 3;
    const int mrow = (w & 3) * 16;
    const int nc4  = (w >> 2) * 32;
    const int nc8  = (w >> 2) * 64;
    const int grow = t >> 2, gj = t & 3;

    for (int tile = blockIdx.x; tile < ntiles; tile += gridDim.x) {
        const int base = tile * TE;
        __syncthreads();
        {
            const int n = base + grow;
            __half* dr = sX + grow * XSH;
            if (n < NN) {
                const float* xr = nf + (long)n * DD;
                #pragma unroll
                for (int i = 0; i < 8; i++) {
                    int d0 = gj * 4 + i * 16;
                    float4 v = *(const float4*)(xr + d0);
                    *(half2*)(dr + d0) =
                        __floats2half2_rn(fmaxf(v.x, 0.f), fmaxf(v.y, 0.f));
                    *(half2*)(dr + d0 + 2) =
                        __floats2half2_rn(fmaxf(v.z, 0.f), fmaxf(v.w, 0.f));
                }
            } else {
                #pragma unroll
                for (int i = 0; i < 8; i++) {
                    int d0 = gj * 4 + i * 16;
                    *(half2*)(dr + d0)     = __floats2half2_rn(0.f, 0.f);
                    *(half2*)(dr + d0 + 2) = __floats2half2_rn(0.f, 0.f);
                }
            }
        }
        __syncthreads();

        // L1 + g_acc + bias
        {
            float c[4][4] = {};
            wgemm<DD, XSH, XSH, 4>(sX, sW1T, mrow, nc4, g, tig, c);
            int n0 = base + mrow + g;
            int n1 = n0 + 8;
            #pragma unroll
            for (int j = 0; j < 4; j++) {
                int col = nc4 + j * 8 + 2 * tig;
                float b0 = sb1[col], b1 = sb1[col + 1];
                __half* o0 = sH1 + (mrow + g) * HSH + col;
                __half* o1 = sH1 + (mrow + g + 8) * HSH + col;
                if (n0 < NN) {
                    float2 ga = *(const float2*)(g_acc + (long)n0 * HH + col);
                    *(half2*)o0 = __floats2half2_rn(
                        fmaxf(c[j][0] + ga.x + b0, 0.f),
                        fmaxf(c[j][1] + ga.y + b1, 0.f));
                } else *(half2*)o0 = __floats2half2_rn(0.f, 0.f);
                if (n1 < NN) {
                    float2 ga = *(const float2*)(g_acc + (long)n1 * HH + col);
                    *(half2*)o1 = __floats2half2_rn(
                        fmaxf(c[j][2] + ga.x + b0, 0.f),
                        fmaxf(c[j][3] + ga.y + b1, 0.f));
                } else *(half2*)o1 = __floats2half2_rn(0.f, 0.f);
            }
        }
        __syncthreads();

        // L2
        {
            float c[4][4] = {};
            wgemm<HH, HSH, HSH, 4>(sH1, sW2T, mrow, nc4, g, tig, c);
            epi_store<4>(c, sH2, HSH, sb2, mrow, nc4, g, tig);
        }
        __syncthreads();

        // L3 -> out (fp32)
        {
            float c[8][4] = {};
            wgemm<HH, HSH, HSH, 8>(sH2, sW3T, mrow, nc8, g, tig, c);
            int n0 = base + mrow + g;
            int n1 = n0 + 8;
            #pragma unroll
            for (int j = 0; j < 8; j++) {
                int col = nc8 + j * 8 + 2 * tig;
                float b0 = sb3[col], b1 = sb3[col + 1];
                if (n0 < NN) {
                    float2 v; v.x = c[j][0] + b0; v.y = c[j][1] + b1;
                    *(float2*)(out + (long)n0 * DD + col) = v;
                }
                if (n1 < NN) {
                    float2 v; v.x = c[j][2] + b0; v.y = c[j][3] + b1;
                    *(float2*)(out + (long)n1 * DD + col) = v;
                }
            }
        }
    }
}

extern "C" void kernel_launch(void* const* d_in, const int* in_sizes, int n_in,
                              void* d_out, int out_size) {
    const float* nf   = (const float*)d_in[0];
    const int*   esrc = (const int*)d_in[1];
    const int*   edst = (const int*)d_in[2];
    const int*   etyp = (const int*)d_in[3];
    const float* Wr1  = (const float*)d_in[4];
    const float* br1  = (const float*)d_in[5];
    const float* Wr2  = (const float*)d_in[6];
    const float* br2  = (const float*)d_in[7];
    const float* Wr3  = (const float*)d_in[8];
    const float* br3  = (const float*)d_in[9];
    const float* Wn1  = (const float*)d_in[10];
    const float* bn1  = (const float*)d_in[11];
    const float* Wn2  = (const float*)d_in[12];
    const float* bn2  = (const float*)d_in[13];
    const float* Wn3  = (const float*)d_in[14];
    const float* bn3  = (const float*)d_in[15];
    float* out = (float*)d_out;

    cudaFuncSetAttribute(edge_kernel, cudaFuncAttributeMaxDynamicSharedMemorySize, E_TOTAL);
    cudaFuncSetAttribute(node_kernel, cudaFuncAttributeMaxDynamicSharedMemorySize, N_TOTAL);

    zero_kernel<<<(NN * HH / 4 + NTHREADS - 1) / NTHREADS, NTHREADS>>>();
    bin_kernel<<<(NE + NTHREADS - 1) / NTHREADS, NTHREADS>>>(etyp);
    edge_kernel<<<2 * NSM, NTHREADS, E_TOTAL>>>(nf, esrc, edst,
                                                Wr1, br1, Wr2, br2, Wr3, br3, Wn1);
    node_kernel<<<2 * NSM, NTHREADS, N_TOTAL>>>(nf, Wn1, bn1, Wn2, bn2, Wn3, bn3, out);
}